// round 15
// baseline (speedup 1.0000x reference)
#include <cuda_runtime.h>
#include <cstdint>

// Wilson Dslash, 32^4 lattice, half-spinor formulation.
// R14 structure (own-line U record via cp.async.bulk; t-hops via shuffles;
// bwd-U scalar coalesced LDG->STS; output bulk-store) PLUS:
// all 6 x/y/z psi neighbor t-lines (contiguous 1536B each) now travel on the
// bulk-copy engine too, double-buffered one stage ahead (R11 pipeline), so
// the ~432 l1tex wavefronts of strided psi LDG.128 vanish. Own psi line for
// the t-hops also arrives by TMA (issued at stage 5). Dynamic smem
// (17.7KB/warp, 70.8KB/block -> 3 blocks/SM).

#define LAT 32
#define VOL (LAT * LAT * LAT * LAT)
#define NT 128
#define NWARP (NT / 32)
#define WBYTES 17696
#define SMEM_BYTES (WBYTES * NWARP)

__device__ __forceinline__ uint32_t smem_u32(const void* p) {
    uint32_t a;
    asm("{ .reg .u64 t; cvta.to.shared.u64 t, %1; cvt.u32.u64 %0, t; }"
        : "=r"(a) : "l"(p));
    return a;
}
__device__ __forceinline__ void mbar_wait(uint32_t mb, int phase) {
    uint32_t done;
    do {
        asm volatile(
            "{ .reg .pred p; "
            "mbarrier.try_wait.parity.acquire.cta.shared::cta.b64 p, [%1], %2; "
            "selp.b32 %0, 1, 0, p; }"
            : "=r"(done) : "r"(mb), "r"(phase) : "memory");
    } while (!done);
}

// projection + color matvec + spin reconstruction for one (mu,hop) stage.
template<int MU, int HOP>
__device__ __forceinline__ void stage_compute(
    const float* pr, const float* pi,
    const float* ur, const float* ui,
    float* accr, float* acci)
{
    const float s = HOP ? 1.f : -1.f;
    float hr0[3], hi0[3], hr1[3], hi1[3];
#pragma unroll
    for (int c = 0; c < 3; c++) {
        if (MU == 0) {
            hr0[c] = pr[c]   - s * pi[9+c];  hi0[c] = pi[c]   + s * pr[9+c];
            hr1[c] = pr[3+c] - s * pi[6+c];  hi1[c] = pi[3+c] + s * pr[6+c];
        } else if (MU == 1) {
            hr0[c] = pr[c]   - s * pr[9+c];  hi0[c] = pi[c]   - s * pi[9+c];
            hr1[c] = pr[3+c] + s * pr[6+c];  hi1[c] = pi[3+c] + s * pi[6+c];
        } else if (MU == 2) {
            hr0[c] = pr[c]   - s * pi[6+c];  hi0[c] = pi[c]   + s * pr[6+c];
            hr1[c] = pr[3+c] + s * pi[9+c];  hi1[c] = pi[3+c] - s * pr[9+c];
        } else {
            hr0[c] = pr[c]   + s * pr[6+c];  hi0[c] = pi[c]   + s * pi[6+c];
            hr1[c] = pr[3+c] + s * pr[9+c];  hi1[c] = pi[3+c] + s * pi[9+c];
        }
    }

    float xr0[3], xi0[3], xr1[3], xi1[3];
#pragma unroll
    for (int i = 0; i < 3; i++) {
        float r0 = 0.f, m0 = 0.f, r1 = 0.f, m1 = 0.f;
#pragma unroll
        for (int j = 0; j < 3; j++) {
            if (HOP == 0) {
                const float a = ur[3*i+j], b = ui[3*i+j];
                r0 += a * hr0[j] - b * hi0[j];
                m0 += a * hi0[j] + b * hr0[j];
                r1 += a * hr1[j] - b * hi1[j];
                m1 += a * hi1[j] + b * hr1[j];
            } else {
                const float a = ur[3*j+i], b = ui[3*j+i];   // U^dag
                r0 += a * hr0[j] + b * hi0[j];
                m0 += a * hi0[j] - b * hr0[j];
                r1 += a * hr1[j] + b * hi1[j];
                m1 += a * hi1[j] - b * hr1[j];
            }
        }
        xr0[i] = r0; xi0[i] = m0; xr1[i] = r1; xi1[i] = m1;
    }

#pragma unroll
    for (int i = 0; i < 3; i++) {
        accr[i]   += xr0[i];  acci[i]   += xi0[i];
        accr[3+i] += xr1[i];  acci[3+i] += xi1[i];
        if (MU == 0) {
            accr[6+i] += s * xi1[i];  acci[6+i] -= s * xr1[i];
            accr[9+i] += s * xi0[i];  acci[9+i] -= s * xr0[i];
        } else if (MU == 1) {
            accr[6+i] += s * xr1[i];  acci[6+i] += s * xi1[i];
            accr[9+i] -= s * xr0[i];  acci[9+i] -= s * xi0[i];
        } else if (MU == 2) {
            accr[6+i] += s * xi0[i];  acci[6+i] -= s * xr0[i];
            accr[9+i] -= s * xi1[i];  acci[9+i] += s * xr1[i];
        } else {
            accr[6+i] += s * xr0[i];  acci[6+i] += s * xi0[i];
            accr[9+i] += s * xr1[i];  acci[9+i] += s * xi1[i];
        }
    }
}

__device__ __forceinline__ void unpack12(float4 a0, float4 a1, float4 a2, float* d) {
    d[0]=a0.x; d[1]=a0.y; d[2]=a0.z; d[3]=a0.w;
    d[4]=a1.x; d[5]=a1.y; d[6]=a1.z; d[7]=a1.w;
    d[8]=a2.x; d[9]=a2.y; d[10]=a2.z; d[11]=a2.w;
}

__global__ __launch_bounds__(NT, 3)
void dslash_kernel(const float* __restrict__ psi_re, const float* __restrict__ psi_im,
                   const float* __restrict__ U_re,   const float* __restrict__ U_im,
                   float* __restrict__ out)
{
    extern __shared__ __align__(16) char smem_raw[];

    const int lane   = threadIdx.x & 31;
    const int w      = threadIdx.x >> 5;
    const int base_w = blockIdx.x * NT + w * 32;   // 32-aligned t-line base

    // per-warp smem carve:
    //   oU  : own-line U record, 2 x 1152 floats (4608B each)
    //   pBuf: psi double buffer, 2 bufs x (re 384 + im 384) floats
    //   bR/bI: bwd-line U mu-slice, 288 floats each
    //   mbars: 3 x u64 (own-U, psi buf0, psi buf1)
    char* wb = smem_raw + w * WBYTES;
    float* oUr  = (float*)wb;
    float* oUi  = oUr + 1152;
    float* pBuf = oUi + 1152;
    float* bR   = pBuf + 1536;
    float* bI   = bR + 288;
    unsigned long long* mbars = (unsigned long long*)(bI + 288);

    float4* oUr4 = (float4*)oUr;
    float4* oUi4 = (float4*)oUi;

    const uint32_t mbU = smem_u32(&mbars[0]);
    const uint32_t mb0 = smem_u32(&mbars[1]);
    const uint32_t mb1 = smem_u32(&mbars[2]);
    const uint32_t aOr = smem_u32(oUr);
    const uint32_t aOi = smem_u32(oUi);
    const uint32_t aP00 = smem_u32(pBuf);         // buf0 re
    const uint32_t aP01 = smem_u32(pBuf + 384);   // buf0 im
    const uint32_t aP10 = smem_u32(pBuf + 768);   // buf1 re
    const uint32_t aP11 = smem_u32(pBuf + 1152);  // buf1 im

    // neighbor line offsets for mu = 0,1,2
    int fd[3], bd[3];
#pragma unroll
    for (int mu = 0; mu < 3; mu++) {
        const int shift = (mu == 0) ? 15 : (mu == 1) ? 10 : 5;
        const int sm = 1 << shift;
        const int cmw = (base_w >> shift) & 31;
        fd[mu] = (cmw == 31) ? -31 * sm : sm;
        bd[mu] = (cmw == 0)  ?  31 * sm : -sm;
    }

    // hoisted per-lane offsets for bwd-U staging
    int off9[9];
#pragma unroll
    for (int it = 0; it < 9; it++) {
        const int idx = it * 32 + lane;
        const int l = idx / 9;
        off9[it] = l * 36 + (idx - l * 9);
    }

    // ---- prologue: init mbarriers, bulk-copy own-line U record ----
    if (lane == 0) {
        asm volatile("mbarrier.init.shared.b64 [%0], 1;" :: "r"(mbU) : "memory");
        asm volatile("mbarrier.init.shared.b64 [%0], 1;" :: "r"(mb0) : "memory");
        asm volatile("mbarrier.init.shared.b64 [%0], 1;" :: "r"(mb1) : "memory");
        asm volatile("fence.proxy.async.shared::cta;" ::: "memory");
        asm volatile("mbarrier.arrive.expect_tx.shared.b64 _, [%0], %1;"
                     :: "r"(mbU), "r"(9216) : "memory");
        const float* gr = U_re + (size_t)base_w * 36;
        const float* gi = U_im + (size_t)base_w * 36;
        asm volatile("cp.async.bulk.shared::cluster.global.mbarrier::complete_tx::bytes "
                     "[%0], [%1], %2, [%3];" :: "r"(aOr), "l"(gr), "r"(4608), "r"(mbU) : "memory");
        asm volatile("cp.async.bulk.shared::cluster.global.mbarrier::complete_tx::bytes "
                     "[%0], [%1], %2, [%3];" :: "r"(aOi), "l"(gi), "r"(4608), "r"(mbU) : "memory");
    }

    auto issue_psi = [&](int line, uint32_t mb, uint32_t dR, uint32_t dI) {
        if (lane == 0) {
            asm volatile("fence.proxy.async.shared::cta;" ::: "memory");
            asm volatile("mbarrier.arrive.expect_tx.shared.b64 _, [%0], %1;"
                         :: "r"(mb), "r"(3072) : "memory");
            const float* sr = psi_re + (size_t)line * 12;
            const float* si = psi_im + (size_t)line * 12;
            asm volatile("cp.async.bulk.shared::cluster.global.mbarrier::complete_tx::bytes "
                         "[%0], [%1], %2, [%3];" :: "r"(dR), "l"(sr), "r"(1536), "r"(mb) : "memory");
            asm volatile("cp.async.bulk.shared::cluster.global.mbarrier::complete_tx::bytes "
                         "[%0], [%1], %2, [%3];" :: "r"(dI), "l"(si), "r"(1536), "r"(mb) : "memory");
        }
    };

    // prologue psi: stage 0's line (bwd mu=0) into buf0
    issue_psi(base_w + bd[0], mb0, aP00, aP01);

    float accr[12], acci[12];
#pragma unroll
    for (int k = 0; k < 12; k++) { accr[k] = 0.f; acci[k] = 0.f; }

    // read a site spinor from a psi smem buffer (stride-3 float4, conflict-free)
#define READ_PSI(BUF, SL, PRV, PIV)                                               \
    {                                                                             \
        const float4* PR4 = (const float4*)(pBuf + (BUF) * 768);                  \
        const float4* PI4 = (const float4*)(pBuf + (BUF) * 768 + 384);            \
        unpack12(PR4[(SL)*3+0], PR4[(SL)*3+1], PR4[(SL)*3+2], PRV);               \
        unpack12(PI4[(SL)*3+0], PI4[(SL)*3+1], PI4[(SL)*3+2], PIV);               \
    }

    // ================= Phase A: backward hops mu=0,1,2 =================
#define BWD_STAGE(MU, BUF, MBARW, PHASE, ISSUE_STMT)                              \
    {                                                                             \
        ISSUE_STMT;                                                               \
        const int nbl = base_w + bd[MU];                                          \
        const float* gr = U_re + (size_t)nbl * 36 + (MU) * 9;                     \
        const float* gi = U_im + (size_t)nbl * 36 + (MU) * 9;                     \
        float tr[9], ti[9];                                                       \
        _Pragma("unroll") for (int it = 0; it < 9; it++) tr[it] = gr[off9[it]];   \
        _Pragma("unroll") for (int it = 0; it < 9; it++) ti[it] = gi[off9[it]];   \
        _Pragma("unroll") for (int it = 0; it < 9; it++) bR[it*32+lane] = tr[it]; \
        _Pragma("unroll") for (int it = 0; it < 9; it++) bI[it*32+lane] = ti[it]; \
        __syncwarp();                                                             \
        mbar_wait(MBARW, PHASE);                                                  \
        float pr[12], pi[12];                                                     \
        READ_PSI(BUF, lane, pr, pi)                                               \
        stage_compute<(MU), 1>(pr, pi, bR + lane*9, bI + lane*9, accr, acci);     \
        __syncwarp();                                                             \
    }

    BWD_STAGE(0, 0, mb0, 0, issue_psi(base_w + bd[1], mb1, aP10, aP11))
    BWD_STAGE(1, 1, mb1, 0, issue_psi(base_w + bd[2], mb0, aP00, aP01))
    BWD_STAGE(2, 0, mb0, 1, issue_psi(base_w + fd[0], mb1, aP10, aP11))

    // ---- own-line U record now needed ----
    mbar_wait(mbU, 0);

    // ================= Phase B: forward hops mu=0,1,2 =================
    // own-U row: words [9*MU, 9*MU+9) -> float4s C0..C0+2 with offset R
#define FWD_STAGE(MU, C0, R, BUF, MBARW, PHASE, ISSUE_STMT)                       \
    {                                                                             \
        ISSUE_STMT;                                                               \
        mbar_wait(MBARW, PHASE);                                                  \
        float pr[12], pi[12];                                                     \
        READ_PSI(BUF, lane, pr, pi)                                               \
        float wr[12], wi[12];                                                     \
        unpack12(oUr4[lane*9 + (C0)], oUr4[lane*9 + (C0)+1],                      \
                 oUr4[lane*9 + (C0)+2], wr);                                      \
        unpack12(oUi4[lane*9 + (C0)], oUi4[lane*9 + (C0)+1],                      \
                 oUi4[lane*9 + (C0)+2], wi);                                      \
        stage_compute<(MU), 0>(pr, pi, wr + (R), wi + (R), accr, acci);           \
        __syncwarp();                                                             \
    }

    FWD_STAGE(0, 0, 0, 1, mb1, 1, issue_psi(base_w + fd[1], mb0, aP00, aP01))
    FWD_STAGE(1, 2, 1, 0, mb0, 0, issue_psi(base_w + fd[2], mb1, aP10, aP11))
    FWD_STAGE(2, 4, 2, 1, mb1, 0, issue_psi(base_w, mb0, aP00, aP01))

    // ================= Phase C: t-hops (mu=3, t == lane) =================
    {
        mbar_wait(mb0, 1);   // own psi line in buf0
        float opr[12], opi[12];
        READ_PSI(0, lane, opr, opi)

        // fwd t-hop: neighbor = lane+1 (wrap); U row mu=3 at site lane
        {
            const int src = (lane + 1) & 31;
            float pr[12], pi[12];
#pragma unroll
            for (int k = 0; k < 12; k++) {
                pr[k] = __shfl_sync(0xffffffffu, opr[k], src);
                pi[k] = __shfl_sync(0xffffffffu, opi[k], src);
            }
            float wr[12], wi[12];   // mu=3: C0=6, R=3
            unpack12(oUr4[lane*9+6], oUr4[lane*9+7], oUr4[lane*9+8], wr);
            unpack12(oUi4[lane*9+6], oUi4[lane*9+7], oUi4[lane*9+8], wi);
            stage_compute<3, 0>(pr, pi, wr + 3, wi + 3, accr, acci);
        }
        // bwd t-hop: neighbor = lane-1, U (dagger) at site lane-1
        {
            const int src = (lane + 31) & 31;
            float pr[12], pi[12];
#pragma unroll
            for (int k = 0; k < 12; k++) {
                pr[k] = __shfl_sync(0xffffffffu, opr[k], src);
                pi[k] = __shfl_sync(0xffffffffu, opi[k], src);
            }
            const int usl = (lane + 31) & 31;
            float wr[12], wi[12];
            unpack12(oUr4[usl*9+6], oUr4[usl*9+7], oUr4[usl*9+8], wr);
            unpack12(oUi4[usl*9+6], oUi4[usl*9+7], oUi4[usl*9+8], wi);
            stage_compute<3, 1>(pr, pi, wr + 3, wi + 3, accr, acci);
        }
    }

    // ---- scale by -0.5, stage into the (dead) own-U buffer, bulk-store ----
    __syncwarp();   // all lanes done reading oUr/oUi before overwrite
#pragma unroll
    for (int r = 0; r < 3; r++) {
        float4 a, b;
        a.x = -0.5f * accr[4*r+0]; a.y = -0.5f * accr[4*r+1];
        a.z = -0.5f * accr[4*r+2]; a.w = -0.5f * accr[4*r+3];
        b.x = -0.5f * acci[4*r+0]; b.y = -0.5f * acci[4*r+1];
        b.z = -0.5f * acci[4*r+2]; b.w = -0.5f * acci[4*r+3];
        oUr4[lane * 3 + r] = a;     // stride-3 float4: conflict-free
        oUi4[lane * 3 + r] = b;
    }
    __syncwarp();
    if (lane == 0) {
        asm volatile("fence.proxy.async.shared::cta;" ::: "memory");
        float* gr = out + (size_t)base_w * 12;
        float* gi = out + (size_t)(VOL + base_w) * 12;
        asm volatile("cp.async.bulk.global.shared::cta.bulk_group [%0], [%1], %2;"
                     :: "l"(gr), "r"(aOr), "r"(1536) : "memory");
        asm volatile("cp.async.bulk.global.shared::cta.bulk_group [%0], [%1], %2;"
                     :: "l"(gi), "r"(aOi), "r"(1536) : "memory");
        asm volatile("cp.async.bulk.commit_group;" ::: "memory");
        asm volatile("cp.async.bulk.wait_group 0;" ::: "memory");
    }
}

extern "C" void kernel_launch(void* const* d_in, const int* in_sizes, int n_in,
                              void* d_out, int out_size) {
    const float* psi_re = (const float*)d_in[0];
    const float* psi_im = (const float*)d_in[1];
    const float* U_re   = (const float*)d_in[2];
    const float* U_im   = (const float*)d_in[3];
    // d_in[4..7]: projector matrices — fixed DeGrand-Rossi I -/+ gamma_mu,
    // rank-2 structure exploited analytically.
    float* out = (float*)d_out;

    cudaFuncSetAttribute(dslash_kernel,
                         cudaFuncAttributeMaxDynamicSharedMemorySize, SMEM_BYTES);
    dslash_kernel<<<VOL / NT, NT, SMEM_BYTES>>>(psi_re, psi_im, U_re, U_im, out);
}

// round 16
// speedup vs baseline: 1.2128x; 1.2128x over previous
#include <cuda_runtime.h>
#include <cstdint>

// Wilson Dslash, 32^4 lattice, half-spinor formulation. R14 structure:
//  - OWN t-line U record (4608B contiguous/array) via cp.async.bulk at warp
//    start; serves fwd mu=0..2 and both t-hops. Readback 3x LDS.128/row.
//  - BWD U lines (mu=0,1,2): scalar coalesced LDG->STS, conflict-free readback.
//  - psi: direct LDG.128 for x/y/z neighbors (issued early); t-hops via __shfl.
//  - output: scale -> conflict-free STS into dead own-U buffer -> bulk store.
// R16 change: __launch_bounds__(128, 5) -> 102-reg cap -> 20 warps/SM (+25%),
// smem 46.1KB x 5 = 225KB fits the 228KB carveout. Staging temporaries fused
// to shorten live ranges and help the 102-reg target land without spills.

#define LAT 32
#define VOL (LAT * LAT * LAT * LAT)
#define NT 128
#define NWARP (NT / 32)

__device__ __forceinline__ uint32_t smem_u32(const void* p) {
    uint32_t a;
    asm("{ .reg .u64 t; cvta.to.shared.u64 t, %1; cvt.u32.u64 %0, t; }"
        : "=r"(a) : "l"(p));
    return a;
}
__device__ __forceinline__ void mbar_wait(uint32_t mb, int phase) {
    uint32_t done;
    do {
        asm volatile(
            "{ .reg .pred p; "
            "mbarrier.try_wait.parity.acquire.cta.shared::cta.b64 p, [%1], %2; "
            "selp.b32 %0, 1, 0, p; }"
            : "=r"(done) : "r"(mb), "r"(phase) : "memory");
    } while (!done);
}

// projection + color matvec + spin reconstruction for one (mu,hop) stage.
template<int MU, int HOP>
__device__ __forceinline__ void stage_compute(
    const float* pr, const float* pi,
    const float* ur, const float* ui,
    float* accr, float* acci)
{
    const float s = HOP ? 1.f : -1.f;
    float hr0[3], hi0[3], hr1[3], hi1[3];
#pragma unroll
    for (int c = 0; c < 3; c++) {
        if (MU == 0) {
            hr0[c] = pr[c]   - s * pi[9+c];  hi0[c] = pi[c]   + s * pr[9+c];
            hr1[c] = pr[3+c] - s * pi[6+c];  hi1[c] = pi[3+c] + s * pr[6+c];
        } else if (MU == 1) {
            hr0[c] = pr[c]   - s * pr[9+c];  hi0[c] = pi[c]   - s * pi[9+c];
            hr1[c] = pr[3+c] + s * pr[6+c];  hi1[c] = pi[3+c] + s * pi[6+c];
        } else if (MU == 2) {
            hr0[c] = pr[c]   - s * pi[6+c];  hi0[c] = pi[c]   + s * pr[6+c];
            hr1[c] = pr[3+c] + s * pi[9+c];  hi1[c] = pi[3+c] - s * pr[9+c];
        } else {
            hr0[c] = pr[c]   + s * pr[6+c];  hi0[c] = pi[c]   + s * pi[6+c];
            hr1[c] = pr[3+c] + s * pr[9+c];  hi1[c] = pi[3+c] + s * pi[9+c];
        }
    }

    float xr0[3], xi0[3], xr1[3], xi1[3];
#pragma unroll
    for (int i = 0; i < 3; i++) {
        float r0 = 0.f, m0 = 0.f, r1 = 0.f, m1 = 0.f;
#pragma unroll
        for (int j = 0; j < 3; j++) {
            if (HOP == 0) {
                const float a = ur[3*i+j], b = ui[3*i+j];
                r0 += a * hr0[j] - b * hi0[j];
                m0 += a * hi0[j] + b * hr0[j];
                r1 += a * hr1[j] - b * hi1[j];
                m1 += a * hi1[j] + b * hr1[j];
            } else {
                const float a = ur[3*j+i], b = ui[3*j+i];   // U^dag
                r0 += a * hr0[j] + b * hi0[j];
                m0 += a * hi0[j] - b * hr0[j];
                r1 += a * hr1[j] + b * hi1[j];
                m1 += a * hi1[j] - b * hr1[j];
            }
        }
        xr0[i] = r0; xi0[i] = m0; xr1[i] = r1; xi1[i] = m1;
    }

#pragma unroll
    for (int i = 0; i < 3; i++) {
        accr[i]   += xr0[i];  acci[i]   += xi0[i];
        accr[3+i] += xr1[i];  acci[3+i] += xi1[i];
        if (MU == 0) {
            accr[6+i] += s * xi1[i];  acci[6+i] -= s * xr1[i];
            accr[9+i] += s * xi0[i];  acci[9+i] -= s * xr0[i];
        } else if (MU == 1) {
            accr[6+i] += s * xr1[i];  acci[6+i] += s * xi1[i];
            accr[9+i] -= s * xr0[i];  acci[9+i] -= s * xi0[i];
        } else if (MU == 2) {
            accr[6+i] += s * xi0[i];  acci[6+i] -= s * xr0[i];
            accr[9+i] -= s * xi1[i];  acci[9+i] += s * xr1[i];
        } else {
            accr[6+i] += s * xr0[i];  acci[6+i] += s * xi0[i];
            accr[9+i] += s * xr1[i];  acci[9+i] += s * xi1[i];
        }
    }
}

__device__ __forceinline__ void unpack12(float4 a0, float4 a1, float4 a2, float* d) {
    d[0]=a0.x; d[1]=a0.y; d[2]=a0.z; d[3]=a0.w;
    d[4]=a1.x; d[5]=a1.y; d[6]=a1.z; d[7]=a1.w;
    d[8]=a2.x; d[9]=a2.y; d[10]=a2.z; d[11]=a2.w;
}

__global__ __launch_bounds__(NT, 5)
void dslash_kernel(const float* __restrict__ psi_re, const float* __restrict__ psi_im,
                   const float* __restrict__ U_re,   const float* __restrict__ U_im,
                   float* __restrict__ out)
{
    __shared__ float4 sOR[NWARP][288];   // own-line U_re record (32 sites x 36 floats)
    __shared__ float4 sOI[NWARP][288];
    __shared__ float  sBr[NWARP][288];   // bwd-line U mu-slice (32 sites x 9)
    __shared__ float  sBi[NWARP][288];
    __shared__ __align__(8) unsigned long long mbar[NWARP];

    const int lane   = threadIdx.x & 31;
    const int w      = threadIdx.x >> 5;
    const int base_w = blockIdx.x * NT + w * 32;   // 32-aligned t-line base

    const float4* psi_re4 = reinterpret_cast<const float4*>(psi_re);
    const float4* psi_im4 = reinterpret_cast<const float4*>(psi_im);

    const uint32_t mb = smem_u32(&mbar[w]);
    const uint32_t oR = smem_u32(&sOR[w][0]);
    const uint32_t oI = smem_u32(&sOI[w][0]);

    // ---- prologue: bulk-copy the own-line U record (both arrays) ----
    if (lane == 0) {
        asm volatile("mbarrier.init.shared.b64 [%0], 1;" :: "r"(mb) : "memory");
        asm volatile("fence.proxy.async.shared::cta;" ::: "memory");
        asm volatile("mbarrier.arrive.expect_tx.shared.b64 _, [%0], %1;"
                     :: "r"(mb), "r"(9216) : "memory");
        const float* gr = U_re + (size_t)base_w * 36;
        const float* gi = U_im + (size_t)base_w * 36;
        asm volatile("cp.async.bulk.shared::cluster.global.mbarrier::complete_tx::bytes "
                     "[%0], [%1], %2, [%3];" :: "r"(oR), "l"(gr), "r"(4608), "r"(mb) : "memory");
        asm volatile("cp.async.bulk.shared::cluster.global.mbarrier::complete_tx::bytes "
                     "[%0], [%1], %2, [%3];" :: "r"(oI), "l"(gi), "r"(4608), "r"(mb) : "memory");
    }

    float accr[12], acci[12];
#pragma unroll
    for (int k = 0; k < 12; k++) { accr[k] = 0.f; acci[k] = 0.f; }

    // ================= Phase A: backward hops mu=0,1,2 =================
    // (prologue bulk copy's latency hides under these scalar-staged stages)
#define BWD_STAGE(MU, SHIFT)                                                      \
    {                                                                             \
        const int sm = 1 << (SHIFT);                                              \
        const int cmw = (base_w >> (SHIFT)) & 31;                                 \
        const int nbl = base_w + ((cmw == 0) ? 31 * sm : -sm);                    \
        const int nb = nbl + lane;                                                \
        /* psi neighbor: direct LDG.128, issued early */                          \
        const float4 a0 = psi_re4[(size_t)nb * 3 + 0];                            \
        const float4 a1 = psi_re4[(size_t)nb * 3 + 1];                            \
        const float4 a2 = psi_re4[(size_t)nb * 3 + 2];                            \
        const float4 b0 = psi_im4[(size_t)nb * 3 + 0];                            \
        const float4 b1 = psi_im4[(size_t)nb * 3 + 1];                            \
        const float4 b2 = psi_im4[(size_t)nb * 3 + 2];                            \
        /* bwd U mu-slice: coalesced scalar LDG -> STS (short temp liveness) */   \
        const float* gr = U_re + (size_t)nbl * 36 + (MU) * 9;                     \
        const float* gi = U_im + (size_t)nbl * 36 + (MU) * 9;                     \
        _Pragma("unroll") for (int it = 0; it < 9; it++) {                        \
            const int idx = it * 32 + lane;                                       \
            const int l = idx / 9;                                                \
            const int o = l * 36 + (idx - l * 9);                                 \
            sBr[w][idx] = gr[o];                                                  \
            sBi[w][idx] = gi[o];                                                  \
        }                                                                         \
        __syncwarp();                                                             \
        float pr[12], pi[12];                                                     \
        unpack12(a0, a1, a2, pr);                                                 \
        unpack12(b0, b1, b2, pi);                                                 \
        stage_compute<(MU), 1>(pr, pi, &sBr[w][lane*9], &sBi[w][lane*9],          \
                               accr, acci);                                       \
        __syncwarp();                                                             \
    }

    BWD_STAGE(0, 15)
    BWD_STAGE(1, 10)
    BWD_STAGE(2, 5)

    // ---- own-line U record now needed: wait for the bulk copy ----
    mbar_wait(mb, 0);

    // ================= Phase B: forward hops mu=0,1,2 =================
    // own-U row: words [9*MU, 9*MU+9) -> float4s C0..C0+2 with offset R
#define FWD_STAGE(MU, SHIFT, C0, R)                                               \
    {                                                                             \
        const int sm = 1 << (SHIFT);                                              \
        const int cmw = (base_w >> (SHIFT)) & 31;                                 \
        const int nb = base_w + ((cmw == 31) ? -31 * sm : sm) + lane;             \
        const float4 a0 = psi_re4[(size_t)nb * 3 + 0];                            \
        const float4 a1 = psi_re4[(size_t)nb * 3 + 1];                            \
        const float4 a2 = psi_re4[(size_t)nb * 3 + 2];                            \
        const float4 b0 = psi_im4[(size_t)nb * 3 + 0];                            \
        const float4 b1 = psi_im4[(size_t)nb * 3 + 1];                            \
        const float4 b2 = psi_im4[(size_t)nb * 3 + 2];                            \
        float wr[12], wi[12];                                                     \
        unpack12(sOR[w][lane*9 + (C0)], sOR[w][lane*9 + (C0)+1],                  \
                 sOR[w][lane*9 + (C0)+2], wr);                                    \
        unpack12(sOI[w][lane*9 + (C0)], sOI[w][lane*9 + (C0)+1],                  \
                 sOI[w][lane*9 + (C0)+2], wi);                                    \
        float pr[12], pi[12];                                                     \
        unpack12(a0, a1, a2, pr);                                                 \
        unpack12(b0, b1, b2, pi);                                                 \
        stage_compute<(MU), 0>(pr, pi, wr + (R), wi + (R), accr, acci);           \
    }

    FWD_STAGE(0, 15, 0, 0)
    FWD_STAGE(1, 10, 2, 1)
    FWD_STAGE(2, 5, 4, 2)

    // ================= Phase C: t-hops (mu=3, t == lane) =================
    {
        const int site = base_w + lane;
        float opr[12], opi[12];
        unpack12(psi_re4[(size_t)site*3+0], psi_re4[(size_t)site*3+1],
                 psi_re4[(size_t)site*3+2], opr);
        unpack12(psi_im4[(size_t)site*3+0], psi_im4[(size_t)site*3+1],
                 psi_im4[(size_t)site*3+2], opi);

        // fwd t-hop: neighbor = lane+1 (wrap); U row mu=3 at site lane
        {
            const int src = (lane + 1) & 31;
            float pr[12], pi[12];
#pragma unroll
            for (int k = 0; k < 12; k++) {
                pr[k] = __shfl_sync(0xffffffffu, opr[k], src);
                pi[k] = __shfl_sync(0xffffffffu, opi[k], src);
            }
            float wr[12], wi[12];   // mu=3: C0=6, R=3
            unpack12(sOR[w][lane*9+6], sOR[w][lane*9+7], sOR[w][lane*9+8], wr);
            unpack12(sOI[w][lane*9+6], sOI[w][lane*9+7], sOI[w][lane*9+8], wi);
            stage_compute<3, 0>(pr, pi, wr + 3, wi + 3, accr, acci);
        }
        // bwd t-hop: neighbor = lane-1, U (dagger) at site lane-1
        {
            const int src = (lane + 31) & 31;
            float pr[12], pi[12];
#pragma unroll
            for (int k = 0; k < 12; k++) {
                pr[k] = __shfl_sync(0xffffffffu, opr[k], src);
                pi[k] = __shfl_sync(0xffffffffu, opi[k], src);
            }
            const int usl = (lane + 31) & 31;
            float wr[12], wi[12];
            unpack12(sOR[w][usl*9+6], sOR[w][usl*9+7], sOR[w][usl*9+8], wr);
            unpack12(sOI[w][usl*9+6], sOI[w][usl*9+7], sOI[w][usl*9+8], wi);
            stage_compute<3, 1>(pr, pi, wr + 3, wi + 3, accr, acci);
        }
    }

    // ---- scale by -0.5, stage into the (dead) own-U buffer, bulk-store ----
    __syncwarp();   // all lanes done reading sOR/sOI before overwrite
#pragma unroll
    for (int r = 0; r < 3; r++) {
        float4 a, b;
        a.x = -0.5f * accr[4*r+0]; a.y = -0.5f * accr[4*r+1];
        a.z = -0.5f * accr[4*r+2]; a.w = -0.5f * accr[4*r+3];
        b.x = -0.5f * acci[4*r+0]; b.y = -0.5f * acci[4*r+1];
        b.z = -0.5f * acci[4*r+2]; b.w = -0.5f * acci[4*r+3];
        sOR[w][lane * 3 + r] = a;     // stride-3 float4: conflict-free
        sOI[w][lane * 3 + r] = b;
    }
    __syncwarp();
    if (lane == 0) {
        asm volatile("fence.proxy.async.shared::cta;" ::: "memory");
        float* gr = out + (size_t)base_w * 12;
        float* gi = out + (size_t)(VOL + base_w) * 12;
        asm volatile("cp.async.bulk.global.shared::cta.bulk_group [%0], [%1], %2;"
                     :: "l"(gr), "r"(oR), "r"(1536) : "memory");
        asm volatile("cp.async.bulk.global.shared::cta.bulk_group [%0], [%1], %2;"
                     :: "l"(gi), "r"(oI), "r"(1536) : "memory");
        asm volatile("cp.async.bulk.commit_group;" ::: "memory");
        asm volatile("cp.async.bulk.wait_group 0;" ::: "memory");
    }
}

extern "C" void kernel_launch(void* const* d_in, const int* in_sizes, int n_in,
                              void* d_out, int out_size) {
    const float* psi_re = (const float*)d_in[0];
    const float* psi_im = (const float*)d_in[1];
    const float* U_re   = (const float*)d_in[2];
    const float* U_im   = (const float*)d_in[3];
    // d_in[4..7]: projector matrices — fixed DeGrand-Rossi I -/+ gamma_mu,
    // rank-2 structure exploited analytically.
    float* out = (float*)d_out;

    dslash_kernel<<<VOL / NT, NT>>>(psi_re, psi_im, U_re, U_im, out);
}